// round 1
// baseline (speedup 1.0000x reference)
#include <cuda_runtime.h>
#include <cuda_bf16.h>
#include <math.h>

#define NB 256
#define NS 64
#define NT 20
#define NE 100
#define NH 1024
#define NV 32000
#define N3H (3 * NH)
#define TD (NT - 1)   // 19 decoder steps

// ------------------------- scratch (device globals) -------------------------
__device__ float g_emb_enc[NB * NS * NE];          // 6.5 MB
__device__ float g_gi_enc[(size_t)NB * NS * N3H];  // 201 MB
__device__ float g_gh[NB * N3H];                   // 3 MB
__device__ float g_h0[NB * NH];
__device__ float g_h1[NB * NH];
__device__ float g_ctx[NB * NH];
__device__ float g_ctxgi[NB * N3H];
__device__ float g_demb[NB * TD * NE];
__device__ float g_gidec[(size_t)NB * TD * N3H];   // 60 MB
__device__ float g_logits[(size_t)NB * NV];        // 32.8 MB
__device__ float g_hd0[NB * NH];
__device__ float g_hd1[NB * NH];
__device__ float g_ce[TD * NB];
__device__ float g_mask[TD * NB];

// ------------------------- generic SGEMM: C = A * B^T + bias ----------------
// A: [M,K] row-major (lda), B: [N,K] row-major (ldb), C: [M,N] row-major.
#define GBM 64
#define GBN 64
#define GBK 16

__global__ __launch_bounds__(256) void gemm_abt(
    int M, int N, int K,
    const float* __restrict__ A, int lda,
    const float* __restrict__ Bm, int ldb,
    const float* __restrict__ bias,
    float* __restrict__ C)
{
    __shared__ __align__(16) float As[GBK][GBM + 4];
    __shared__ __align__(16) float Bs[GBK][GBN + 4];

    int tid = threadIdx.x;
    int tx = tid & 15;       // 0..15  -> N direction (4 cols each)
    int ty = tid >> 4;       // 0..15  -> M direction (4 rows each)
    int row0 = blockIdx.y * GBM;
    int col0 = blockIdx.x * GBN;

    float acc[4][4] = {};

    for (int k0 = 0; k0 < K; k0 += GBK) {
#pragma unroll
        for (int i = 0; i < 4; i++) {
            int e = tid + i * 256;   // 0..1023
            int r = e >> 4;          // 0..63
            int c = e & 15;          // 0..15
            int gk = k0 + c;
            int gr = row0 + r;
            int gn = col0 + r;
            As[c][r] = (gr < M && gk < K) ? A[(size_t)gr * lda + gk] : 0.0f;
            Bs[c][r] = (gn < N && gk < K) ? Bm[(size_t)gn * ldb + gk] : 0.0f;
        }
        __syncthreads();

#pragma unroll
        for (int kk = 0; kk < GBK; kk++) {
            float4 av4 = *(const float4*)&As[kk][ty * 4];
            float4 bv4 = *(const float4*)&Bs[kk][tx * 4];
            float av[4] = {av4.x, av4.y, av4.z, av4.w};
            float bv[4] = {bv4.x, bv4.y, bv4.z, bv4.w};
#pragma unroll
            for (int i = 0; i < 4; i++)
#pragma unroll
                for (int j = 0; j < 4; j++)
                    acc[i][j] = fmaf(av[i], bv[j], acc[i][j]);
        }
        __syncthreads();
    }

#pragma unroll
    for (int i = 0; i < 4; i++) {
        int gr = row0 + ty * 4 + i;
        if (gr >= M) continue;
#pragma unroll
        for (int j = 0; j < 4; j++) {
            int gc = col0 + tx * 4 + j;
            if (gc < N) {
                float v = acc[i][j];
                if (bias) v += bias[gc];
                C[(size_t)gr * N + gc] = v;
            }
        }
    }
}

// ------------------------- gathers --------------------------------------------
__global__ __launch_bounds__(256) void gather_emb_enc(
    const int* __restrict__ tokens, const float* __restrict__ table,
    float* __restrict__ out)
{
    int idx = blockIdx.x * blockDim.x + threadIdx.x;
    if (idx >= NB * NS * NE) return;
    int tk = tokens[idx / NE];
    out[idx] = table[tk * NE + (idx % NE)];
}

__global__ __launch_bounds__(256) void gather_demb(
    const int* __restrict__ targets, const float* __restrict__ E_dec,
    float* __restrict__ out)
{
    int idx = blockIdx.x * blockDim.x + threadIdx.x;
    if (idx >= NB * TD * NE) return;
    int m = idx / NE;          // b * TD + t
    int t = m % TD;
    int b = m / TD;
    int tok = (t == 0) ? 1 : targets[b * NT + t];
    out[idx] = E_dec[tok * NE + (idx % NE)];
}

// ------------------------- GRU cells ------------------------------------------
__device__ __forceinline__ float sigmoidf_(float x) {
    return 1.0f / (1.0f + expf(-x));
}

__global__ __launch_bounds__(256) void gru_cell_enc(
    const float* __restrict__ gi_all, int t,
    const float* __restrict__ gh,
    const float* __restrict__ h_old,
    float* __restrict__ h_new,
    const int* __restrict__ lengths,
    float* __restrict__ context)
{
    int idx = blockIdx.x * blockDim.x + threadIdx.x;   // over NB*NH
    int b = idx >> 10;
    int j = idx & (NH - 1);
    const float* gib = gi_all + ((size_t)(b * NS + t)) * N3H;
    const float* ghb = gh + b * N3H;
    float ir = gib[j], iz = gib[NH + j], in = gib[2 * NH + j];
    float hr = ghb[j], hz = ghb[NH + j], hn = ghb[2 * NH + j];
    float h = h_old[idx];
    float r = sigmoidf_(ir + hr);
    float z = sigmoidf_(iz + hz);
    float n = tanhf(in + r * hn);
    float hv = (1.0f - z) * n + z * h;
    h_new[idx] = hv;
    if (t == lengths[b] - 1) context[idx] = hv;
}

__global__ __launch_bounds__(256) void gru_cell_dec(
    const float* __restrict__ gi_emb, const float* __restrict__ ctx_gi, int t,
    const float* __restrict__ gh,
    const float* __restrict__ h_old,
    float* __restrict__ h_new)
{
    int idx = blockIdx.x * blockDim.x + threadIdx.x;
    int b = idx >> 10;
    int j = idx & (NH - 1);
    const float* gib = gi_emb + ((size_t)(b * TD + t)) * N3H;
    const float* gcb = ctx_gi + b * N3H;
    const float* ghb = gh + b * N3H;
    float ir = gib[j] + gcb[j];
    float iz = gib[NH + j] + gcb[NH + j];
    float in = gib[2 * NH + j] + gcb[2 * NH + j];
    float hr = ghb[j], hz = ghb[NH + j], hn = ghb[2 * NH + j];
    float h = h_old[idx];
    float r = sigmoidf_(ir + hr);
    float z = sigmoidf_(iz + hz);
    float n = tanhf(in + r * hn);
    h_new[idx] = (1.0f - z) * n + z * h;
}

// ------------------------- softmax cross-entropy ------------------------------
__global__ __launch_bounds__(256) void ce_kernel(
    const float* __restrict__ logits, const int* __restrict__ targets, int t,
    float* __restrict__ ce, float* __restrict__ mask)
{
    int b = blockIdx.x;
    int tid = threadIdx.x;
    const float* row = logits + (size_t)b * NV;

    float m = -1e30f, s = 0.0f;
    for (int i = tid; i < NV; i += 256) {
        float v = row[i];
        if (v > m) { s = s * expf(m - v) + 1.0f; m = v; }
        else       { s += expf(v - m); }
    }

    __shared__ float sm_[256], ss_[256];
    sm_[tid] = m; ss_[tid] = s;
    __syncthreads();
    for (int off = 128; off > 0; off >>= 1) {
        if (tid < off) {
            float m1 = sm_[tid], s1 = ss_[tid];
            float m2 = sm_[tid + off], s2 = ss_[tid + off];
            float M = fmaxf(m1, m2);
            sm_[tid] = M;
            ss_[tid] = s1 * expf(m1 - M) + s2 * expf(m2 - M);
        }
        __syncthreads();
    }
    if (tid == 0) {
        int y = targets[b * NT + (t + 1)];
        float lse = sm_[0] + logf(ss_[0]);
        ce[t * NB + b] = lse - row[y];
        mask[t * NB + b] = (y >= 1) ? 1.0f : 0.0f;
    }
}

__global__ __launch_bounds__(256) void final_loss_kernel(
    const float* __restrict__ ce, const float* __restrict__ mask,
    float* __restrict__ out)
{
    __shared__ float s1[256], s2[256];
    int tid = threadIdx.x;
    float total = 0.0f;
    for (int t = 0; t < TD; t++) {
        s1[tid] = ce[t * NB + tid];
        s2[tid] = mask[t * NB + tid];
        __syncthreads();
        for (int off = 128; off > 0; off >>= 1) {
            if (tid < off) { s1[tid] += s1[tid + off]; s2[tid] += s2[tid + off]; }
            __syncthreads();
        }
        if (tid == 0) total += (s1[0] / (float)NB) * (s2[0] / (float)NB);
        __syncthreads();
    }
    if (tid == 0) out[0] = total / (float)NT;
}

// ------------------------- host orchestration ---------------------------------
extern "C" void kernel_launch(void* const* d_in, const int* in_sizes, int n_in,
                              void* d_out, int out_size)
{
    const int*   inputs  = (const int*)d_in[0];
    const int*   targets = (const int*)d_in[1];
    const int*   lengths = (const int*)d_in[2];
    const float* h0_enc  = (const float*)d_in[3];
    const float* E_enc   = (const float*)d_in[4];
    const float* E_dec   = (const float*)d_in[5];
    const float* W_ih_e  = (const float*)d_in[6];
    const float* W_hh_e  = (const float*)d_in[7];
    const float* b_ih_e  = (const float*)d_in[8];
    const float* b_hh_e  = (const float*)d_in[9];
    const float* W_ih_d  = (const float*)d_in[10];
    const float* W_hh_d  = (const float*)d_in[11];
    const float* b_ih_d  = (const float*)d_in[12];
    const float* b_hh_d  = (const float*)d_in[13];
    const float* W_fc    = (const float*)d_in[14];
    const float* b_fc    = (const float*)d_in[15];
    float* out = (float*)d_out;

    float *p_emb, *p_gienc, *p_gh, *p_h0, *p_h1, *p_ctx, *p_ctxgi;
    float *p_demb, *p_gidec, *p_logits, *p_hd0, *p_hd1, *p_ce, *p_mask;
    cudaGetSymbolAddress((void**)&p_emb,    g_emb_enc);
    cudaGetSymbolAddress((void**)&p_gienc,  g_gi_enc);
    cudaGetSymbolAddress((void**)&p_gh,     g_gh);
    cudaGetSymbolAddress((void**)&p_h0,     g_h0);
    cudaGetSymbolAddress((void**)&p_h1,     g_h1);
    cudaGetSymbolAddress((void**)&p_ctx,    g_ctx);
    cudaGetSymbolAddress((void**)&p_ctxgi,  g_ctxgi);
    cudaGetSymbolAddress((void**)&p_demb,   g_demb);
    cudaGetSymbolAddress((void**)&p_gidec,  g_gidec);
    cudaGetSymbolAddress((void**)&p_logits, g_logits);
    cudaGetSymbolAddress((void**)&p_hd0,    g_hd0);
    cudaGetSymbolAddress((void**)&p_hd1,    g_hd1);
    cudaGetSymbolAddress((void**)&p_ce,     g_ce);
    cudaGetSymbolAddress((void**)&p_mask,   g_mask);

    // ---- encoder: embedding + input-side gates (one big GEMM) ----
    gather_emb_enc<<<(NB * NS * NE + 255) / 256, 256>>>(inputs, E_enc, p_emb);
    {
        dim3 grid(N3H / GBN, (NB * NS) / GBM);
        gemm_abt<<<grid, 256>>>(NB * NS, N3H, NE, p_emb, NE, W_ih_e, NE, b_ih_e, p_gienc);
    }

    // ---- encoder recurrence (64 sequential steps) ----
    dim3 grid_rec(N3H / GBN, NB / GBM);   // 48 x 4
    for (int t = 0; t < NS; t++) {
        const float* hp = (t == 0) ? h0_enc : ((t & 1) ? p_h0 : p_h1);
        float* hn = (t & 1) ? p_h1 : p_h0;
        gemm_abt<<<grid_rec, 256>>>(NB, N3H, NH, hp, NH, W_hh_e, NH, b_hh_e, p_gh);
        gru_cell_enc<<<NB * NH / 256, 256>>>(p_gienc, t, p_gh, hp, hn, lengths, p_ctx);
    }

    // ---- decoder prologue ----
    gemm_abt<<<grid_rec, 256>>>(NB, N3H, NH, p_ctx, NH, W_ih_d + NE, NE + NH,
                                b_ih_d, p_ctxgi);
    gather_demb<<<(NB * TD * NE + 255) / 256, 256>>>(targets, E_dec, p_demb);
    {
        dim3 grid(N3H / GBN, (NB * TD) / GBM);   // 4864 rows = 76 * 64
        gemm_abt<<<grid, 256>>>(NB * TD, N3H, NE, p_demb, NE, W_ih_d, NE + NH,
                                nullptr, p_gidec);
    }

    // ---- decoder recurrence + logits + CE (19 sequential steps) ----
    dim3 grid_fc(NV / GBN, NB / GBM);    // 500 x 4
    for (int t = 0; t < TD; t++) {
        const float* hp = (t == 0) ? p_ctx : ((t & 1) ? p_hd0 : p_hd1);
        float* hn = (t & 1) ? p_hd1 : p_hd0;
        gemm_abt<<<grid_rec, 256>>>(NB, N3H, NH, hp, NH, W_hh_d, NH, b_hh_d, p_gh);
        gru_cell_dec<<<NB * NH / 256, 256>>>(p_gidec, p_ctxgi, t, p_gh, hp, hn);
        gemm_abt<<<grid_fc, 256>>>(NB, NV, NH, hn, NH, W_fc, NH, b_fc, p_logits);
        ce_kernel<<<NB, 256>>>(p_logits, targets, t, p_ce, p_mask);
    }

    final_loss_kernel<<<1, 256>>>(p_ce, p_mask, out);
}

// round 2
// speedup vs baseline: 6.1988x; 6.1988x over previous
#include <cuda_runtime.h>
#include <cuda_bf16.h>
#include <math.h>
#include <stdint.h>

#define NB 256
#define NS 64
#define NT 20
#define NE 100
#define NEP 128            // NE padded to 128
#define NH 1024
#define NV 32000
#define N3H (3 * NH)
#define TD (NT - 1)        // 19 decoder steps
#define BH (NB * NH)

typedef __nv_bfloat16 bf16;

// ------------------------- scratch (device globals) -------------------------
__device__ float g_gi_enc[(size_t)NB * NS * N3H];   // 201 MB
__device__ float g_gh[NB * N3H];
__device__ float g_h[BH];
__device__ float g_hd[BH];
__device__ float g_ctx[BH];
__device__ float g_ctxgi[NB * N3H];
__device__ float g_gidec[(size_t)NB * TD * N3H];    // 60 MB
__device__ float g_logits[(size_t)NB * TD * NV];    // 622 MB
__device__ float g_ce[TD * NB];
__device__ float g_mask[TD * NB];

__device__ bf16 g_embb[(size_t)NB * NS * NEP];      // 4 MB
__device__ bf16 g_dembb[(size_t)NB * TD * NEP];
__device__ bf16 g_hb[BH];
__device__ bf16 g_ctxb[BH];
__device__ bf16 g_hall[(size_t)TD * BH];            // 10 MB
__device__ bf16 wb_hh_e[(size_t)N3H * NH];
__device__ bf16 wb_hh_d[(size_t)N3H * NH];
__device__ bf16 wb_fc[(size_t)NV * NH];             // 64 MB
__device__ bf16 wb_ih_e[(size_t)N3H * NEP];
__device__ bf16 wb_ihd_emb[(size_t)N3H * NEP];
__device__ bf16 wb_ihd_ctx[(size_t)N3H * NH];

// ------------------------- conversion kernels --------------------------------
__global__ __launch_bounds__(256) void f2bf(const float* __restrict__ in,
                                            bf16* __restrict__ out, int n)
{
    for (int i = blockIdx.x * blockDim.x + threadIdx.x; i < n;
         i += gridDim.x * blockDim.x)
        out[i] = __float2bfloat16(in[i]);
}

// out[r][c] = c < kin ? in[r*ldin + koff + c] : 0, out is [rows, kout]
__global__ __launch_bounds__(256) void f2bf_slice(
    const float* __restrict__ in, int ldin, int koff, int kin,
    bf16* __restrict__ out, int kout, int rows)
{
    int n = rows * kout;
    for (int i = blockIdx.x * blockDim.x + threadIdx.x; i < n;
         i += gridDim.x * blockDim.x) {
        int r = i / kout, c = i % kout;
        out[i] = (c < kin) ? __float2bfloat16(in[(size_t)r * ldin + koff + c])
                           : __float2bfloat16(0.0f);
    }
}

// ------------------------- gathers (bf16, padded) -----------------------------
__global__ __launch_bounds__(256) void gather_emb_enc_bf(
    const int* __restrict__ tokens, const float* __restrict__ table,
    bf16* __restrict__ out)
{
    int n = NB * NS * NEP;
    for (int i = blockIdx.x * blockDim.x + threadIdx.x; i < n;
         i += gridDim.x * blockDim.x) {
        int c = i % NEP, m = i / NEP;
        float v = 0.0f;
        if (c < NE) v = table[tokens[m] * NE + c];
        out[i] = __float2bfloat16(v);
    }
}

__global__ __launch_bounds__(256) void gather_demb_bf(
    const int* __restrict__ targets, const float* __restrict__ E_dec,
    bf16* __restrict__ out)
{
    int n = NB * TD * NEP;
    for (int i = blockIdx.x * blockDim.x + threadIdx.x; i < n;
         i += gridDim.x * blockDim.x) {
        int c = i % NEP, m = i / NEP;
        int t = m % TD, b = m / TD;
        float v = 0.0f;
        if (c < NE) {
            int tok = (t == 0) ? 1 : targets[b * NT + t];
            v = E_dec[tok * NE + c];
        }
        out[i] = __float2bfloat16(v);
    }
}

// ------------------------- bf16 tensor-core GEMM: C = A * B^T + bias ----------
// A: [M,K] bf16 row-major (lda), B: [N,K] bf16 row-major (ldb), C fp32 [M,ldc].
// Requires M%64==0, N%64==0, K%32==0, lda%8==0, ldb%8==0.
#define TBM 64
#define TBN 64
#define TBK 32
#define TPAD 8   // bf16 pad -> row stride 40 bf16 = 80B (16B aligned, conflict-free)

__device__ __forceinline__ void cpasync16(void* smem, const void* gmem)
{
    uint32_t s = (uint32_t)__cvta_generic_to_shared(smem);
    asm volatile("cp.async.cg.shared.global [%0], [%1], 16;\n" ::"r"(s), "l"(gmem));
}

#define LDM4(r0, r1, r2, r3, smaddr)                                            \
    asm volatile("ldmatrix.sync.aligned.m8n8.x4.shared.b16 {%0,%1,%2,%3}, [%4];" \
                 : "=r"(r0), "=r"(r1), "=r"(r2), "=r"(r3) : "r"(smaddr))

#define MMA16816(c, a, b0, b1)                                                   \
    asm volatile("mma.sync.aligned.m16n8k16.row.col.f32.bf16.bf16.f32 "          \
                 "{%0,%1,%2,%3}, {%4,%5,%6,%7}, {%8,%9}, {%0,%1,%2,%3};"         \
                 : "+f"(c[0]), "+f"(c[1]), "+f"(c[2]), "+f"(c[3])                \
                 : "r"(a[0]), "r"(a[1]), "r"(a[2]), "r"(a[3]), "r"(b0), "r"(b1))

__global__ __launch_bounds__(128) void hgemm(
    int M, int N, int K,
    const bf16* __restrict__ A, int lda,
    const bf16* __restrict__ B, int ldb,
    const float* __restrict__ bias,
    float* __restrict__ C, int ldc)
{
    __shared__ __align__(16) bf16 As[2][TBM][TBK + TPAD];
    __shared__ __align__(16) bf16 Bs[2][TBN][TBK + TPAD];

    int tid = threadIdx.x;
    int warp = tid >> 5, lane = tid & 31;
    int wm = warp >> 1, wn = warp & 1;        // 2x2 warp grid, 32x32 per warp
    int row0 = blockIdx.y * TBM;
    int col0 = blockIdx.x * TBN;

    float acc[2][4][4] = {};                  // [mt][nj][frag]

    int KT = K / TBK;

    // --- stage 0 prefetch ---
    {
#pragma unroll
        for (int i = 0; i < 2; i++) {
            int v = tid + i * 128;
            int r = v >> 2, c = (v & 3) * 8;
            cpasync16(&As[0][r][c], A + (size_t)(row0 + r) * lda + c);
            cpasync16(&Bs[0][r][c], B + (size_t)(col0 + r) * ldb + c);
        }
        asm volatile("cp.async.commit_group;\n");
    }

    for (int kt = 0; kt < KT; kt++) {
        if (kt + 1 < KT) {
            int st = (kt + 1) & 1;
            int kb = (kt + 1) * TBK;
#pragma unroll
            for (int i = 0; i < 2; i++) {
                int v = tid + i * 128;
                int r = v >> 2, c = (v & 3) * 8;
                cpasync16(&As[st][r][c], A + (size_t)(row0 + r) * lda + kb + c);
                cpasync16(&Bs[st][r][c], B + (size_t)(col0 + r) * ldb + kb + c);
            }
            asm volatile("cp.async.commit_group;\n");
            asm volatile("cp.async.wait_group 1;\n");
        } else {
            asm volatile("cp.async.wait_group 0;\n");
        }
        __syncthreads();

        int st = kt & 1;
#pragma unroll
        for (int k16 = 0; k16 < 2; k16++) {
            uint32_t a[2][4], bb[2][4];
#pragma unroll
            for (int mt = 0; mt < 2; mt++) {
                uint32_t ad = (uint32_t)__cvta_generic_to_shared(
                    &As[st][wm * 32 + mt * 16 + (lane & 15)][k16 * 16 + (lane >> 4) * 8]);
                LDM4(a[mt][0], a[mt][1], a[mt][2], a[mt][3], ad);
            }
#pragma unroll
            for (int nt = 0; nt < 2; nt++) {
                uint32_t bd = (uint32_t)__cvta_generic_to_shared(
                    &Bs[st][wn * 32 + nt * 16 + (lane & 15)][k16 * 16 + (lane >> 4) * 8]);
                LDM4(bb[nt][0], bb[nt][1], bb[nt][2], bb[nt][3], bd);
            }
#pragma unroll
            for (int mt = 0; mt < 2; mt++)
#pragma unroll
                for (int nt = 0; nt < 2; nt++) {
                    MMA16816(acc[mt][nt * 2 + 0], a[mt], bb[nt][0], bb[nt][2]);
                    MMA16816(acc[mt][nt * 2 + 1], a[mt], bb[nt][1], bb[nt][3]);
                }
        }
        __syncthreads();
    }

    // --- epilogue ---
#pragma unroll
    for (int mt = 0; mt < 2; mt++) {
        int rbase = row0 + wm * 32 + mt * 16 + (lane >> 2);
#pragma unroll
        for (int nj = 0; nj < 4; nj++) {
            int nt = nj >> 1, sub = nj & 1;
            int cb = col0 + wn * 32 + nt * 16 + sub * 8 + (lane & 3) * 2;
            float b0 = bias ? bias[cb] : 0.0f;
            float b1 = bias ? bias[cb + 1] : 0.0f;
            float* c4 = acc[mt][nj];
            C[(size_t)rbase * ldc + cb]           = c4[0] + b0;
            C[(size_t)rbase * ldc + cb + 1]       = c4[1] + b1;
            C[(size_t)(rbase + 8) * ldc + cb]     = c4[2] + b0;
            C[(size_t)(rbase + 8) * ldc + cb + 1] = c4[3] + b1;
        }
    }
}

// ------------------------- GRU cells ------------------------------------------
__device__ __forceinline__ float sigmoidf_(float x) {
    return 1.0f / (1.0f + expf(-x));
}

__global__ __launch_bounds__(256) void gru_cell_enc(
    const float* __restrict__ gi_all, int t,
    const float* __restrict__ gh,
    const float* __restrict__ h_old,
    float* __restrict__ h_new, bf16* __restrict__ hb_new,
    const int* __restrict__ lengths,
    float* __restrict__ context, bf16* __restrict__ context_b)
{
    int idx = blockIdx.x * blockDim.x + threadIdx.x;   // over NB*NH
    int b = idx >> 10;
    int j = idx & (NH - 1);
    const float* gib = gi_all + ((size_t)(b * NS + t)) * N3H;
    const float* ghb = gh + b * N3H;
    float ir = gib[j], iz = gib[NH + j], in = gib[2 * NH + j];
    float hr = ghb[j], hz = ghb[NH + j], hn = ghb[2 * NH + j];
    float h = h_old[idx];
    float r = sigmoidf_(ir + hr);
    float z = sigmoidf_(iz + hz);
    float n = tanhf(in + r * hn);
    float hv = (1.0f - z) * n + z * h;
    h_new[idx] = hv;
    hb_new[idx] = __float2bfloat16(hv);
    if (t == lengths[b] - 1) {
        context[idx] = hv;
        context_b[idx] = __float2bfloat16(hv);
    }
}

__global__ __launch_bounds__(256) void gru_cell_dec(
    const float* __restrict__ gi_emb, const float* __restrict__ ctx_gi, int t,
    const float* __restrict__ gh,
    const float* __restrict__ h_old,
    float* __restrict__ h_new, bf16* __restrict__ hall_slot)
{
    int idx = blockIdx.x * blockDim.x + threadIdx.x;
    int b = idx >> 10;
    int j = idx & (NH - 1);
    const float* gib = gi_emb + ((size_t)(b * TD + t)) * N3H;
    const float* gcb = ctx_gi + b * N3H;
    const float* ghb = gh + b * N3H;
    float ir = gib[j] + gcb[j];
    float iz = gib[NH + j] + gcb[NH + j];
    float in = gib[2 * NH + j] + gcb[2 * NH + j];
    float hr = ghb[j], hz = ghb[NH + j], hn = ghb[2 * NH + j];
    float h = h_old[idx];
    float r = sigmoidf_(ir + hr);
    float z = sigmoidf_(iz + hz);
    float n = tanhf(in + r * hn);
    float hv = (1.0f - z) * n + z * h;
    h_new[idx] = hv;
    hall_slot[idx] = __float2bfloat16(hv);
}

// ------------------------- softmax cross-entropy (all rows) -------------------
__global__ __launch_bounds__(256) void ce_all_kernel(
    const float* __restrict__ logits, const int* __restrict__ targets,
    float* __restrict__ ce, float* __restrict__ mask)
{
    int rowi = blockIdx.x;            // rowi = t*NB + b
    int t = rowi / NB, b = rowi % NB;
    int tid = threadIdx.x;
    const float* row = logits + (size_t)rowi * NV;

    float m = -1e30f, s = 0.0f;
    for (int i = tid; i < NV; i += 256) {
        float v = row[i];
        if (v > m) { s = s * expf(m - v) + 1.0f; m = v; }
        else       { s += expf(v - m); }
    }

    __shared__ float sm_[256], ss_[256];
    sm_[tid] = m; ss_[tid] = s;
    __syncthreads();
    for (int off = 128; off > 0; off >>= 1) {
        if (tid < off) {
            float m1 = sm_[tid], s1 = ss_[tid];
            float m2 = sm_[tid + off], s2 = ss_[tid + off];
            float M = fmaxf(m1, m2);
            sm_[tid] = M;
            ss_[tid] = s1 * expf(m1 - M) + s2 * expf(m2 - M);
        }
        __syncthreads();
    }
    if (tid == 0) {
        int y = targets[b * NT + (t + 1)];
        float lse = sm_[0] + logf(ss_[0]);
        ce[rowi] = lse - row[y];
        mask[rowi] = (y >= 1) ? 1.0f : 0.0f;
    }
}

__global__ __launch_bounds__(256) void final_loss_kernel(
    const float* __restrict__ ce, const float* __restrict__ mask,
    float* __restrict__ out)
{
    __shared__ float s1[256], s2[256];
    int tid = threadIdx.x;
    float total = 0.0f;
    for (int t = 0; t < TD; t++) {
        s1[tid] = ce[t * NB + tid];
        s2[tid] = mask[t * NB + tid];
        __syncthreads();
        for (int off = 128; off > 0; off >>= 1) {
            if (tid < off) { s1[tid] += s1[tid + off]; s2[tid] += s2[tid + off]; }
            __syncthreads();
        }
        if (tid == 0) total += (s1[0] / (float)NB) * (s2[0] / (float)NB);
        __syncthreads();
    }
    if (tid == 0) out[0] = total / (float)NT;
}

// ------------------------- host orchestration ---------------------------------
extern "C" void kernel_launch(void* const* d_in, const int* in_sizes, int n_in,
                              void* d_out, int out_size)
{
    const int*   inputs  = (const int*)d_in[0];
    const int*   targets = (const int*)d_in[1];
    const int*   lengths = (const int*)d_in[2];
    const float* h0_enc  = (const float*)d_in[3];
    const float* E_enc   = (const float*)d_in[4];
    const float* E_dec   = (const float*)d_in[5];
    const float* W_ih_e  = (const float*)d_in[6];
    const float* W_hh_e  = (const float*)d_in[7];
    const float* b_ih_e  = (const float*)d_in[8];
    const float* b_hh_e  = (const float*)d_in[9];
    const float* W_ih_d  = (const float*)d_in[10];
    const float* W_hh_d  = (const float*)d_in[11];
    const float* b_ih_d  = (const float*)d_in[12];
    const float* b_hh_d  = (const float*)d_in[13];
    const float* W_fc    = (const float*)d_in[14];
    const float* b_fc    = (const float*)d_in[15];
    float* out = (float*)d_out;

    float *p_gienc, *p_gh, *p_h, *p_hd, *p_ctx, *p_ctxgi, *p_gidec, *p_logits,
          *p_ce, *p_mask;
    bf16 *p_embb, *p_dembb, *p_hb, *p_ctxb, *p_hall;
    bf16 *p_whe, *p_whd, *p_wfc, *p_wie, *p_wide, *p_widc;
    cudaGetSymbolAddress((void**)&p_gienc,  g_gi_enc);
    cudaGetSymbolAddress((void**)&p_gh,     g_gh);
    cudaGetSymbolAddress((void**)&p_h,      g_h);
    cudaGetSymbolAddress((void**)&p_hd,     g_hd);
    cudaGetSymbolAddress((void**)&p_ctx,    g_ctx);
    cudaGetSymbolAddress((void**)&p_ctxgi,  g_ctxgi);
    cudaGetSymbolAddress((void**)&p_gidec,  g_gidec);
    cudaGetSymbolAddress((void**)&p_logits, g_logits);
    cudaGetSymbolAddress((void**)&p_ce,     g_ce);
    cudaGetSymbolAddress((void**)&p_mask,   g_mask);
    cudaGetSymbolAddress((void**)&p_embb,   g_embb);
    cudaGetSymbolAddress((void**)&p_dembb,  g_dembb);
    cudaGetSymbolAddress((void**)&p_hb,     g_hb);
    cudaGetSymbolAddress((void**)&p_ctxb,   g_ctxb);
    cudaGetSymbolAddress((void**)&p_hall,   g_hall);
    cudaGetSymbolAddress((void**)&p_whe,    wb_hh_e);
    cudaGetSymbolAddress((void**)&p_whd,    wb_hh_d);
    cudaGetSymbolAddress((void**)&p_wfc,    wb_fc);
    cudaGetSymbolAddress((void**)&p_wie,    wb_ih_e);
    cudaGetSymbolAddress((void**)&p_wide,   wb_ihd_emb);
    cudaGetSymbolAddress((void**)&p_widc,   wb_ihd_ctx);

    // ---- weight / input conversions to bf16 ----
    f2bf<<<512, 256>>>(W_hh_e, p_whe, N3H * NH);
    f2bf<<<512, 256>>>(W_hh_d, p_whd, N3H * NH);
    f2bf<<<2048, 256>>>(W_fc, p_wfc, NV * NH);
    f2bf_slice<<<256, 256>>>(W_ih_e, NE, 0, NE, p_wie, NEP, N3H);
    f2bf_slice<<<256, 256>>>(W_ih_d, NE + NH, 0, NE, p_wide, NEP, N3H);
    f2bf_slice<<<512, 256>>>(W_ih_d, NE + NH, NE, NH, p_widc, NH, N3H);
    f2bf<<<256, 256>>>(h0_enc, p_hb, BH);
    gather_emb_enc_bf<<<512, 256>>>(inputs, E_enc, p_embb);
    gather_demb_bf<<<256, 256>>>(targets, E_dec, p_dembb);

    // ---- encoder input-side gates: [16384,3072] = embb @ W_ih_e^T ----
    {
        dim3 grid(N3H / TBN, (NB * NS) / TBM);   // 48 x 256
        hgemm<<<grid, 128>>>(NB * NS, N3H, NEP, p_embb, NEP, p_wie, NEP,
                             b_ih_e, p_gienc, N3H);
    }

    // ---- encoder recurrence ----
    dim3 grid_rec(N3H / TBN, NB / TBM);          // 48 x 4
    for (int t = 0; t < NS; t++) {
        const float* hp = (t == 0) ? h0_enc : p_h;
        hgemm<<<grid_rec, 128>>>(NB, N3H, NH, p_hb, NH, p_whe, NH,
                                 b_hh_e, p_gh, N3H);
        gru_cell_enc<<<BH / 256, 256>>>(p_gienc, t, p_gh, hp, p_h, p_hb,
                                        lengths, p_ctx, p_ctxb);
    }

    // ---- decoder prologue ----
    hgemm<<<grid_rec, 128>>>(NB, N3H, NH, p_ctxb, NH, p_widc, NH,
                             b_ih_d, p_ctxgi, N3H);
    {
        dim3 grid(N3H / TBN, (NB * TD) / TBM);   // 48 x 76
        hgemm<<<grid, 128>>>(NB * TD, N3H, NEP, p_dembb, NEP, p_wide, NEP,
                             nullptr, p_gidec, N3H);
    }

    // ---- decoder recurrence (h stored bf16 per step) ----
    for (int t = 0; t < TD; t++) {
        const float* hp = (t == 0) ? p_ctx : p_hd;
        const bf16* hpb = (t == 0) ? p_ctxb : (p_hall + (size_t)(t - 1) * BH);
        hgemm<<<grid_rec, 128>>>(NB, N3H, NH, hpb, NH, p_whd, NH,
                                 b_hh_d, p_gh, N3H);
        gru_cell_dec<<<BH / 256, 256>>>(p_gidec, p_ctxgi, t, p_gh, hp, p_hd,
                                        p_hall + (size_t)t * BH);
    }

    // ---- one big logits GEMM: [4864, 32000] ----
    {
        dim3 grid(NV / TBN, (NB * TD) / TBM);    // 500 x 76
        hgemm<<<grid, 128>>>(NB * TD, NV, NH, p_hall, NH, p_wfc, NH,
                             b_fc, p_logits, NV);
    }

    // ---- CE over all rows + final reduction ----
    ce_all_kernel<<<NB * TD, 256>>>(p_logits, targets, p_ce, p_mask);
    final_loss_kernel<<<1, 256>>>(p_ce, p_mask, out);
}